// round 1
// baseline (speedup 1.0000x reference)
#include <cuda_runtime.h>
#include <cstdint>
#include <cstddef>

#define B_      64
#define LQ      1024
#define LK      1024
#define DH      64
#define QT      8
#define KT      256
#define KPITCH  257
#define NCHUNK  (LK / KT)
#define TEMP_INV 0.125f           // 1 / TEMPERATURE (TEMPERATURE = 8.0)
#define REMOVED  (-1.0e30f)
#define CUTV     (-1.0e29f)

// dynamic smem layout (floats): kT[64*KPITCH] | qT[64*8] | sc[QT*LK]
#define SMEM_FLOATS (64 * KPITCH + 64 * QT + QT * LK)
#define SMEM_BYTES  (SMEM_FLOATS * 4)

__device__ int g_mask_kind;   // 0 = uint8/bool, 1 = int32, 2 = float32

// --------------------------------------------------------------------------
// Classify the mask dtype from its byte pattern (values are only 0/1):
//   int32 : nonzero bytes only at offset%4==0
//   float32: 1.0f = 00 00 80 3F -> nonzero only at offsets 2,3
//   uint8 : nonzero bytes at all offsets
// Deterministic, allocation-free, runs every launch.
// --------------------------------------------------------------------------
__global__ void detect_mask_kernel(const unsigned char* __restrict__ m) {
    __shared__ int nz[4];
    int tid = threadIdx.x;
    if (tid < 4) nz[tid] = 0;
    __syncthreads();
    int ph = tid & 3;       // stride 256 is a multiple of 4 -> phase fixed per thread
    int c = 0;
    for (int i = tid; i < 16384; i += 256)
        if (m[i]) c++;
    if (c) atomicAdd(&nz[ph], c);
    __syncthreads();
    if (tid == 0) {
        int kind;
        if ((nz[1] | nz[2] | nz[3]) == 0)      kind = 1;  // int32
        else if (nz[0] == 0 && nz[3] > 0)      kind = 2;  // float32
        else                                   kind = 0;  // uint8 / bool
        g_mask_kind = kind;
    }
}

// --------------------------------------------------------------------------
// Fused kernel: QK^T (fp32, smem-tiled) -> mask -> sparsemax (Michelot,
// warp-per-row, register-resident) -> sparse attn@V -> write out + attn.
// One CTA handles 8 q-rows of one batch. 256 threads = 8 warps.
// --------------------------------------------------------------------------
extern "C" __global__ void __launch_bounds__(256, 2)
sparse_attn_kernel(const float* __restrict__ q,
                   const float* __restrict__ k,
                   const float* __restrict__ v,
                   const void*  __restrict__ maskp,
                   float* __restrict__ out,
                   float* __restrict__ attn,
                   int write_attn)
{
    extern __shared__ float sm[];
    float* kT = sm;                       // [64][KPITCH]   K chunk, transposed
    float* qT = sm + 64 * KPITCH;         // [64][QT]       Q tile, transposed, pre-scaled
    float* sc = qT + 64 * QT;             // [QT][LK]       scores, later attn probs

    const int tid = threadIdx.x;
    const int b   = blockIdx.y;
    const int q0  = blockIdx.x * QT;
    const int mkind = g_mask_kind;

    // ---- load Q tile (transposed, scaled by 1/temperature) ----
    if (tid < 128) {
        int r  = tid >> 4;       // 0..7  q-row in tile
        int d4 = tid & 15;       // 0..15 float4 index over D
        const float4 qv = *(const float4*)(q + ((size_t)(b * LQ + q0 + r)) * DH + 4 * d4);
        qT[(4 * d4 + 0) * QT + r] = qv.x * TEMP_INV;
        qT[(4 * d4 + 1) * QT + r] = qv.y * TEMP_INV;
        qT[(4 * d4 + 2) * QT + r] = qv.z * TEMP_INV;
        qT[(4 * d4 + 3) * QT + r] = qv.w * TEMP_INV;
    }

    const unsigned char* m8 = (const unsigned char*)maskp;
    const int*           mi = (const int*)maskp;
    const float*         mf = (const float*)maskp;

    // ---- QK^T over 4 chunks of 256 K-rows ----
    for (int c = 0; c < NCHUNK; ++c) {
        __syncthreads();
        // cooperative load of K chunk, transposed into kT[d][kc]
        #pragma unroll
        for (int it = 0; it < KT / 16; ++it) {
            int fi = tid + 256 * it;
            int r  = fi >> 4;    // 0..255 k-row within chunk
            int d4 = fi & 15;
            const float4 kv = *(const float4*)(k + ((size_t)(b * LK + c * KT + r)) * DH + 4 * d4);
            kT[(4 * d4 + 0) * KPITCH + r] = kv.x;
            kT[(4 * d4 + 1) * KPITCH + r] = kv.y;
            kT[(4 * d4 + 2) * KPITCH + r] = kv.z;
            kT[(4 * d4 + 3) * KPITCH + r] = kv.w;
        }
        __syncthreads();

        float acc[QT];
        #pragma unroll
        for (int r = 0; r < QT; ++r) acc[r] = 0.0f;

        #pragma unroll 8
        for (int d = 0; d < DH; ++d) {
            float  kv = kT[d * KPITCH + tid];                 // conflict-free
            float4 qa = *(const float4*)(qT + d * QT);        // broadcast
            float4 qb = *(const float4*)(qT + d * QT + 4);    // broadcast
            acc[0] += qa.x * kv;  acc[1] += qa.y * kv;
            acc[2] += qa.z * kv;  acc[3] += qa.w * kv;
            acc[4] += qb.x * kv;  acc[5] += qb.y * kv;
            acc[6] += qb.z * kv;  acc[7] += qb.w * kv;
        }

        // apply mask, write scores
        int kg = c * KT + tid;
        size_t mbase = ((size_t)b * LQ + q0) * LK + kg;
        #pragma unroll
        for (int r = 0; r < QT; ++r) {
            size_t midx = mbase + (size_t)r * LK;
            bool msk;
            if (mkind == 0)      msk = (m8[midx] != 0);
            else if (mkind == 1) msk = (mi[midx] != 0);
            else                 msk = (mf[midx] != 0.0f);
            sc[r * LK + kg] = msk ? REMOVED : acc[r];
        }
    }
    __syncthreads();

    // ---- per-warp sparsemax (Michelot active-set iteration) ----
    const int w    = tid >> 5;   // warp = q-row in tile
    const int lane = tid & 31;

    float z[32];
    #pragma unroll
    for (int t = 0; t < 32; ++t) z[t] = sc[w * LK + lane + 32 * t];

    float S = 0.0f; int C = 0;
    #pragma unroll
    for (int t = 0; t < 32; ++t) {
        if (z[t] > CUTV) { S += z[t]; C++; }
    }
    #pragma unroll
    for (int o = 16; o; o >>= 1) {
        S += __shfl_xor_sync(0xFFFFFFFFu, S, o);
        C += __shfl_xor_sync(0xFFFFFFFFu, C, o);
    }

    float tau;
    if (C > 0) {
        tau = (S - 1.0f) / (float)C;
        for (int iter = 0; iter < 256; ++iter) {
            // remove entries <= tau
            int removed = 0;
            #pragma unroll
            for (int t = 0; t < 32; ++t) {
                if (z[t] > CUTV && z[t] <= tau) { z[t] = REMOVED; removed++; }
            }
            #pragma unroll
            for (int o = 16; o; o >>= 1)
                removed += __shfl_xor_sync(0xFFFFFFFFu, removed, o);
            if (removed == 0) break;
            // recompute S, C over surviving set
            float s2 = 0.0f; int c2 = 0;
            #pragma unroll
            for (int t = 0; t < 32; ++t) {
                if (z[t] > CUTV) { s2 += z[t]; c2++; }
            }
            #pragma unroll
            for (int o = 16; o; o >>= 1) {
                s2 += __shfl_xor_sync(0xFFFFFFFFu, s2, o);
                c2 += __shfl_xor_sync(0xFFFFFFFFu, c2, o);
            }
            S = s2; C = c2;
            tau = (S - 1.0f) / (float)C;
        }
    } else {
        tau = 1.0e30f;   // fully-masked row -> all probabilities 0
    }

    // ---- probabilities + sparse attn @ V ----
    float2 acc2 = make_float2(0.0f, 0.0f);
    const float* vb = v + (size_t)b * LK * DH;

    #pragma unroll
    for (int t = 0; t < 32; ++t) {
        float p = fmaxf(z[t] - tau, 0.0f);     // removed/masked -> 0
        sc[w * LK + lane + 32 * t] = p;
        unsigned bal = __ballot_sync(0xFFFFFFFFu, p > 0.0f);
        while (bal) {
            int src = __ffs(bal) - 1;
            bal &= bal - 1;
            float pj = __shfl_sync(0xFFFFFFFFu, p, src);
            int j = src + 32 * t;
            const float2 vv = *(const float2*)(vb + (size_t)j * DH + 2 * lane);
            acc2.x += pj * vv.x;
            acc2.y += pj * vv.y;
        }
    }

    // out row: 64 floats, float2 per lane
    *(float2*)(out + ((size_t)(b * LQ + q0 + w)) * DH + 2 * lane) = acc2;

    // attn tile: 8 rows x 1024, coalesced float4 copy from smem
    if (write_attn) {
        __syncthreads();
        const float4* src4 = (const float4*)sc;
        float4* dst4 = (float4*)(attn + ((size_t)b * LQ + q0) * LK);
        #pragma unroll
        for (int r = 0; r < (QT * LK / 4) / 256; ++r)
            dst4[tid + 256 * r] = src4[tid + 256 * r];
    }
}

// --------------------------------------------------------------------------
extern "C" void kernel_launch(void* const* d_in, const int* in_sizes, int n_in,
                              void* d_out, int out_size) {
    const float* q = (const float*)d_in[0];
    const float* k = (const float*)d_in[1];
    const float* v = (const float*)d_in[2];
    const void*  m = d_in[3];

    float* out = (float*)d_out;
    long long out_elems  = (long long)B_ * LQ * DH;
    long long attn_elems = (long long)B_ * LQ * LK;
    int write_attn = ((long long)out_size >= out_elems + attn_elems) ? 1 : 0;
    float* attn = out + (size_t)out_elems;

    detect_mask_kernel<<<1, 256>>>((const unsigned char*)m);

    cudaFuncSetAttribute(sparse_attn_kernel,
                         cudaFuncAttributeMaxDynamicSharedMemorySize, SMEM_BYTES);

    dim3 grid(LQ / QT, B_);
    sparse_attn_kernel<<<grid, 256, SMEM_BYTES>>>(q, k, v, m, out, attn, write_attn);
}

// round 2
// speedup vs baseline: 1.2884x; 1.2884x over previous
#include <cuda_runtime.h>
#include <cstdint>
#include <cstddef>

#define B_      64
#define LQ      1024
#define LK      1024
#define DH      64
#define QT      16
#define CHUNK   128
#define KSP     68            // k_s pitch in floats (68 % 32 == 4 -> conflict-free B-frag LDS)
#define SCP     1032          // sc pitch in floats (1032 % 32 == 8 -> conflict-free STS.64 epilogue)
#define TEMP_INV 0.125f
#define REMOVED  (-1.0e30f)
#define CUTV     (-1.0e29f)

#define SMEM_FLOATS (CHUNK * KSP + QT * SCP)
#define SMEM_BYTES  (SMEM_FLOATS * 4)

__device__ int g_mask_kind;   // 0 = uint8/bool, 1 = int32, 2 = float32

__global__ void detect_mask_kernel(const unsigned char* __restrict__ m) {
    __shared__ int nz[4];
    int tid = threadIdx.x;
    if (tid < 4) nz[tid] = 0;
    __syncthreads();
    int ph = tid & 3;
    int c = 0;
    for (int i = tid; i < 16384; i += 256)
        if (m[i]) c++;
    if (c) atomicAdd(&nz[ph], c);
    __syncthreads();
    if (tid == 0) {
        int kind;
        if ((nz[1] | nz[2] | nz[3]) == 0)      kind = 1;  // int32
        else if (nz[0] == 0 && nz[3] > 0)      kind = 2;  // float32
        else                                   kind = 0;  // uint8 / bool
        g_mask_kind = kind;
    }
}

__device__ __forceinline__ unsigned to_tf32(float x) {
    unsigned r;
    asm("cvt.rna.tf32.f32 %0, %1;" : "=r"(r) : "f"(x));
    return r;
}

__device__ __forceinline__ void mma_tf32(float& d0, float& d1, float& d2, float& d3,
                                         unsigned a0, unsigned a1, unsigned a2, unsigned a3,
                                         unsigned b0, unsigned b1) {
    asm("mma.sync.aligned.m16n8k8.row.col.f32.tf32.tf32.f32 "
        "{%0,%1,%2,%3}, {%4,%5,%6,%7}, {%8,%9}, {%0,%1,%2,%3};"
        : "+f"(d0), "+f"(d1), "+f"(d2), "+f"(d3)
        : "r"(a0), "r"(a1), "r"(a2), "r"(a3), "r"(b0), "r"(b1));
}

// --------------------------------------------------------------------------
// QK^T via 3xTF32 mma.sync (fp32-accurate) -> mask -> sparsemax (Michelot)
// -> sparse attn@V -> out + attn.  One CTA = 16 q-rows of one batch.
// 256 threads / 8 warps; warp w owns score-matrix rows w and w+8.
// --------------------------------------------------------------------------
extern "C" __global__ void __launch_bounds__(256, 2)
sparse_attn_kernel(const float* __restrict__ q,
                   const float* __restrict__ k,
                   const float* __restrict__ v,
                   const void*  __restrict__ maskp,
                   float* __restrict__ out,
                   float* __restrict__ attn,
                   int write_attn)
{
    extern __shared__ float sm[];
    float* k_s = sm;                  // [CHUNK][KSP]  K chunk, row-major (col, d)
    float* sc  = sm + CHUNK * KSP;    // [QT][SCP]     scores -> probs

    const int tid  = threadIdx.x;
    const int w    = tid >> 5;
    const int lane = tid & 31;
    const int b    = blockIdx.y;
    const int q0   = blockIdx.x * QT;
    const int mkind = g_mask_kind;

    // ---- precompute A fragments (Q tile), hi/lo tf32 split, scaled ----
    // m16n8k8 A layout: a0=(r,c) a1=(r+8,c) a2=(r,c+4) a3=(r+8,c+4); r=lane/4, c=lane%4
    unsigned ahi[8][4], alo[8][4];
    {
        const int ar0 = q0 + (lane >> 2);
        const float* qb0 = q + ((size_t)(b * LQ + ar0)) * DH + (lane & 3);
        const float* qb1 = qb0 + 8 * DH;
        #pragma unroll
        for (int ks = 0; ks < 8; ++ks) {
            float x0 = qb0[ks * 8]     * TEMP_INV;   // a0
            float x1 = qb1[ks * 8]     * TEMP_INV;   // a1
            float x2 = qb0[ks * 8 + 4] * TEMP_INV;   // a2
            float x3 = qb1[ks * 8 + 4] * TEMP_INV;   // a3
            unsigned h0 = to_tf32(x0), h1 = to_tf32(x1), h2 = to_tf32(x2), h3 = to_tf32(x3);
            ahi[ks][0] = h0; ahi[ks][1] = h1; ahi[ks][2] = h2; ahi[ks][3] = h3;
            alo[ks][0] = to_tf32(x0 - __uint_as_float(h0));
            alo[ks][1] = to_tf32(x1 - __uint_as_float(h1));
            alo[ks][2] = to_tf32(x2 - __uint_as_float(h2));
            alo[ks][3] = to_tf32(x3 - __uint_as_float(h3));
        }
    }

    // ---- QK^T over 8 chunks of 128 K-rows ----
    for (int c = 0; c < LK / CHUNK; ++c) {
        __syncthreads();
        // load K chunk: k_s[r][d], coalesced LDG.128
        #pragma unroll
        for (int it = 0; it < (CHUNK * 16) / 256; ++it) {
            int fi = tid + 256 * it;
            int r  = fi >> 4;       // 0..127
            int d4 = fi & 15;
            const float4 kv = *(const float4*)(k + ((size_t)(b * LK + c * CHUNK + r)) * DH + 4 * d4);
            *(float4*)(k_s + r * KSP + 4 * d4) = kv;
        }
        __syncthreads();

        #pragma unroll
        for (int ct = 0; ct < CHUNK / 64; ++ct) {
            const int nb = ct * 64 + w * 8;     // col-tile base within chunk
            float d0 = 0.f, d1 = 0.f, d2 = 0.f, d3 = 0.f;
            // B layout (col-major 8x8): b0 = B[k=lane%4][n=lane/4], b1 at k+4
            const float* bp = k_s + (nb + (lane >> 2)) * KSP + (lane & 3);
            #pragma unroll
            for (int ks = 0; ks < 8; ++ks) {
                float b0f = bp[ks * 8];
                float b1f = bp[ks * 8 + 4];
                unsigned bh0 = to_tf32(b0f);
                unsigned bh1 = to_tf32(b1f);
                unsigned bl0 = to_tf32(b0f - __uint_as_float(bh0));
                unsigned bl1 = to_tf32(b1f - __uint_as_float(bh1));
                mma_tf32(d0, d1, d2, d3, ahi[ks][0], ahi[ks][1], ahi[ks][2], ahi[ks][3], bl0, bl1);
                mma_tf32(d0, d1, d2, d3, alo[ks][0], alo[ks][1], alo[ks][2], alo[ks][3], bh0, bh1);
                mma_tf32(d0, d1, d2, d3, ahi[ks][0], ahi[ks][1], ahi[ks][2], ahi[ks][3], bh0, bh1);
            }
            // C layout: c0=(r, 2c) c1=(r, 2c+1) c2=(r+8, 2c) c3=(r+8, 2c+1)
            int row0 = lane >> 2;
            int gc   = c * CHUNK + nb + 2 * (lane & 3);
            *(float2*)(sc + row0 * SCP + gc)       = make_float2(d0, d1);
            *(float2*)(sc + (row0 + 8) * SCP + gc) = make_float2(d2, d3);
        }
    }
    __syncthreads();

    // ---- mask pass (coalesced) ----
    {
        const unsigned char* m8 = (const unsigned char*)maskp;
        const int*           mi = (const int*)maskp;
        const float*         mf = (const float*)maskp;
        size_t mbase = ((size_t)b * LQ + q0) * LK;
        #pragma unroll
        for (int it = 0; it < QT * LK / 256; ++it) {
            int idx = tid + 256 * it;
            int row = idx >> 10;
            int col = idx & 1023;
            size_t midx = mbase + (size_t)row * LK + col;
            bool msk;
            if (mkind == 0)      msk = (m8[midx] != 0);
            else if (mkind == 1) msk = (mi[midx] != 0);
            else                 msk = (mf[midx] != 0.0f);
            if (msk) sc[row * SCP + col] = REMOVED;
        }
    }
    __syncthreads();

    // ---- sparsemax + sparse attn@V, warp w handles rows w and w+8 ----
    const float* vb = v + (size_t)b * LK * DH;
    #pragma unroll
    for (int rr = 0; rr < 2; ++rr) {
        const int row = w + 8 * rr;

        float z[32];
        #pragma unroll
        for (int t = 0; t < 32; ++t) z[t] = sc[row * SCP + lane + 32 * t];

        float S = 0.0f; int C = 0;
        #pragma unroll
        for (int t = 0; t < 32; ++t)
            if (z[t] > CUTV) { S += z[t]; C++; }
        #pragma unroll
        for (int o = 16; o; o >>= 1) {
            S += __shfl_xor_sync(0xFFFFFFFFu, S, o);
            C += __shfl_xor_sync(0xFFFFFFFFu, C, o);
        }

        float tau;
        if (C > 0) {
            tau = (S - 1.0f) / (float)C;
            for (int iter = 0; iter < 256; ++iter) {
                int removed = 0;
                #pragma unroll
                for (int t = 0; t < 32; ++t)
                    if (z[t] > CUTV && z[t] <= tau) { z[t] = REMOVED; removed++; }
                #pragma unroll
                for (int o = 16; o; o >>= 1)
                    removed += __shfl_xor_sync(0xFFFFFFFFu, removed, o);
                if (removed == 0) break;
                float s2 = 0.0f; int c2 = 0;
                #pragma unroll
                for (int t = 0; t < 32; ++t)
                    if (z[t] > CUTV) { s2 += z[t]; c2++; }
                #pragma unroll
                for (int o = 16; o; o >>= 1) {
                    s2 += __shfl_xor_sync(0xFFFFFFFFu, s2, o);
                    c2 += __shfl_xor_sync(0xFFFFFFFFu, c2, o);
                }
                S = s2; C = c2;
                tau = (S - 1.0f) / (float)C;
            }
        } else {
            tau = 1.0e30f;
        }

        float2 acc2 = make_float2(0.0f, 0.0f);
        #pragma unroll
        for (int t = 0; t < 32; ++t) {
            float p = fmaxf(z[t] - tau, 0.0f);
            sc[row * SCP + lane + 32 * t] = p;
            unsigned bal = __ballot_sync(0xFFFFFFFFu, p > 0.0f);
            while (bal) {
                int src = __ffs(bal) - 1;
                bal &= bal - 1;
                float pj = __shfl_sync(0xFFFFFFFFu, p, src);
                int j = src + 32 * t;
                const float2 vv = *(const float2*)(vb + (size_t)j * DH + 2 * lane);
                acc2.x += pj * vv.x;
                acc2.y += pj * vv.y;
            }
        }
        *(float2*)(out + ((size_t)(b * LQ + q0 + row)) * DH + 2 * lane) = acc2;
    }

    // ---- attn tile writeback (16 rows x 1024), coalesced ----
    if (write_attn) {
        __syncthreads();
        float* dst = attn + ((size_t)b * LQ + q0) * LK;
        #pragma unroll
        for (int it = 0; it < QT * (LK / 4) / 256; ++it) {
            int idx = tid + 256 * it;
            int row = idx >> 8;          // 256 float4 per row
            int c4  = idx & 255;
            float4 vle = *(const float4*)(sc + row * SCP + 4 * c4);
            *(float4*)(dst + (size_t)row * LK + 4 * c4) = vle;
        }
    }
}

// --------------------------------------------------------------------------
extern "C" void kernel_launch(void* const* d_in, const int* in_sizes, int n_in,
                              void* d_out, int out_size) {
    const float* q = (const float*)d_in[0];
    const float* k = (const float*)d_in[1];
    const float* v = (const float*)d_in[2];
    const void*  m = d_in[3];

    float* out = (float*)d_out;
    long long out_elems  = (long long)B_ * LQ * DH;
    long long attn_elems = (long long)B_ * LQ * LK;
    int write_attn = ((long long)out_size >= out_elems + attn_elems) ? 1 : 0;
    float* attn = out + (size_t)out_elems;

    detect_mask_kernel<<<1, 256>>>((const unsigned char*)m);

    cudaFuncSetAttribute(sparse_attn_kernel,
                         cudaFuncAttributeMaxDynamicSharedMemorySize, SMEM_BYTES);

    dim3 grid(LQ / QT, B_);
    sparse_attn_kernel<<<grid, 256, SMEM_BYTES>>>(q, k, v, m, out, attn, write_attn);
}